// round 1
// baseline (speedup 1.0000x reference)
#include <cuda_runtime.h>
#include <cstdint>

// Problem constants
#define H   2048
#define F   1408
#define FS  2816
#define E   8
#define T   2048
#define GSTRIDE 2816          // unified G row stride (max of F, FS)
#define MAXROWS 7424          // padded routed rows (<=5120) + shared (2048) + slack

// GEMM tiling
#define BM 128
#define BN 64
#define BK 32
#define PAD 36                // smem row stride in floats (16B-aligned rows, conflict-free frags)

// -------------------- scratch (alloc-free rule: __device__ globals) --------------------
__device__ float g_XG[(size_t)MAXROWS * H];        // gathered tokens, tf32-rounded
__device__ float g_G [(size_t)MAXROWS * GSTRIDE];  // SwiGLU intermediate, tf32-rounded
__device__ float g_Y [(size_t)MAXROWS * H];        // per-(token,expert) down-proj output
__device__ int   g_cnt[E];
__device__ int   g_cursor[E];
__device__ int   g_row0[E + 1];
__device__ int   g_mtiles[E + 1];
__device__ int   g_rowof[2 * T];
__device__ int   g_tke[2 * T];
__device__ float g_tkw[2 * T];

// -------------------- helpers --------------------
__device__ __forceinline__ uint32_t f2t_bits(float x) {
    uint32_t u;
    asm("cvt.rna.tf32.f32 %0, %1;" : "=r"(u) : "f"(x));
    return u;
}
__device__ __forceinline__ float f2tf(float x) { return __uint_as_float(f2t_bits(x)); }

__device__ __forceinline__ void cpa16(float* s, const float* g) {
    uint32_t sa = (uint32_t)__cvta_generic_to_shared(s);
    asm volatile("cp.async.cg.shared.global [%0], [%1], 16;" :: "r"(sa), "l"(g));
}
__device__ __forceinline__ void cp_commit() { asm volatile("cp.async.commit_group;"); }
__device__ __forceinline__ void cp_wait0()  { asm volatile("cp.async.wait_group 0;"); }

__device__ __forceinline__ void mma8(float* d, const uint32_t* a, const uint32_t* b) {
    asm volatile(
        "mma.sync.aligned.m16n8k8.row.col.f32.tf32.tf32.f32 "
        "{%0,%1,%2,%3},{%4,%5,%6,%7},{%8,%9},{%0,%1,%2,%3};"
        : "+f"(d[0]), "+f"(d[1]), "+f"(d[2]), "+f"(d[3])
        : "r"(a[0]), "r"(a[1]), "r"(a[2]), "r"(a[3]), "r"(b[0]), "r"(b[1]));
}

// -------------------- kernel 0: zero counters --------------------
__global__ void k_zero() {
    if (threadIdx.x < E) g_cnt[threadIdx.x] = 0;
}

// -------------------- kernel 1: gating (fp32 exact) --------------------
__global__ void __launch_bounds__(256) k_gate(const float* __restrict__ x,
                                              const float* __restrict__ gw) {
    int warp = (blockIdx.x * blockDim.x + threadIdx.x) >> 5;
    int lane = threadIdx.x & 31;
    if (warp >= T) return;
    const float* xr = x + (size_t)warp * H;
    float xv[H / 32];
#pragma unroll
    for (int i = 0; i < H / 32; i++) xv[i] = xr[lane + i * 32];
    float sc[E];
#pragma unroll
    for (int e = 0; e < E; e++) {
        const float* w = gw + (size_t)e * H;
        float a = 0.f;
#pragma unroll
        for (int i = 0; i < H / 32; i++) a += xv[i] * w[lane + i * 32];
#pragma unroll
        for (int o = 16; o > 0; o >>= 1) a += __shfl_xor_sync(0xffffffffu, a, o);
        sc[e] = a;
    }
    if (lane == 0) {
        float mx = sc[0];
#pragma unroll
        for (int e = 1; e < E; e++) mx = fmaxf(mx, sc[e]);
        float s = 0.f;
#pragma unroll
        for (int e = 0; e < E; e++) { sc[e] = expf(sc[e] - mx); s += sc[e]; }
        float inv_s = 1.f / s;
#pragma unroll
        for (int e = 0; e < E; e++) sc[e] *= inv_s;
        // top-2, jax tie-break (lowest index wins on equality via strict >)
        int e0 = 0;
#pragma unroll
        for (int e = 1; e < E; e++) if (sc[e] > sc[e0]) e0 = e;
        int e1 = -1;
#pragma unroll
        for (int e = 0; e < E; e++)
            if (e != e0 && (e1 < 0 || sc[e] > sc[e1])) e1 = e;
        float w0 = sc[e0], w1 = sc[e1];
        float inv = 1.f / (w0 + w1 + 1e-20f);
        g_tke[2 * warp]     = e0;
        g_tke[2 * warp + 1] = e1;
        g_tkw[2 * warp]     = w0 * inv;
        g_tkw[2 * warp + 1] = w1 * inv;
        atomicAdd(&g_cnt[e0], 1);
        atomicAdd(&g_cnt[e1], 1);
    }
}

// -------------------- kernel 2: scan (padded offsets) --------------------
__global__ void k_scan() {
    if (threadIdx.x == 0 && blockIdx.x == 0) {
        int off = 0;
        for (int e = 0; e < E; e++) {
            g_row0[e]   = off;
            g_cursor[e] = off;
            int mt = (g_cnt[e] + 127) >> 7;
            g_mtiles[e] = mt;
            off += mt << 7;
        }
        g_row0[E]   = off;       // shared-expert region start
        g_mtiles[E] = T >> 7;    // 16
    }
}

// -------------------- kernel 3: gather/scatter rows (tf32-rounded) --------------------
__global__ void __launch_bounds__(256) k_gather(const float* __restrict__ x) {
    __shared__ int sp;
    int b = blockIdx.x;
    int t, p;
    if (b < 2 * T) {
        if (threadIdx.x == 0) {
            int e = g_tke[b];
            int q = atomicAdd(&g_cursor[e], 1);
            g_rowof[b] = q;
            sp = q;
        }
        __syncthreads();
        p = sp;
        t = b >> 1;
    } else {
        t = b - 2 * T;
        p = g_row0[E] + t;
    }
    const float4* src = (const float4*)(x + (size_t)t * H);
    float4* dst = (float4*)(g_XG + (size_t)p * H);
    for (int i = threadIdx.x; i < H / 4; i += blockDim.x) {
        float4 v = src[i];
        v.x = f2tf(v.x); v.y = f2tf(v.y); v.z = f2tf(v.z); v.w = f2tf(v.w);
        dst[i] = v;
    }
}

// -------------------- kernel 4: grouped GEMM1 (gate+up fused, SwiGLU epilogue) --------
// C1 = A @ Wg^T, C2 = A @ Wu^T, G = tf32(silu(C1) * C2).  K = H for every group.
__global__ void __launch_bounds__(256) k_gemm1(const float* __restrict__ wg,
                                               const float* __restrict__ wu,
                                               const float* __restrict__ swg,
                                               const float* __restrict__ swu) {
    int grp = blockIdx.z;
    if ((int)blockIdx.y >= g_mtiles[grp]) return;
    int Nloc  = (grp < E) ? F : FS;
    int nBase = blockIdx.x * BN;
    if (nBase >= Nloc) return;
    const float* Bgp = (grp < E) ? wg + (size_t)grp * F * H : swg;
    const float* Bup = (grp < E) ? wu + (size_t)grp * F * H : swu;
    int aRow = g_row0[grp] + blockIdx.y * BM;

    extern __shared__ float sm[];
    float* sA  = sm;                         // 2 * BM*PAD
    float* sBg = sm + 2 * BM * PAD;          // 2 * BN*PAD
    float* sBu = sBg + 2 * BN * PAD;         // 2 * BN*PAD

    int tid = threadIdx.x;
    const int KT = H / BK;                   // 64
    float4 rBg[2], rBu[2];

    auto loadA = [&](int kt, int buf) {
        const float* gA = g_XG + (size_t)aRow * H + kt * BK;
        float* s = sA + buf * BM * PAD;
#pragma unroll
        for (int i = 0; i < 4; i++) {
            int idx = tid + i * 256;
            int r = idx >> 3, c = (idx & 7) * 4;
            cpa16(s + r * PAD + c, gA + (size_t)r * H + c);
        }
    };
    auto ldgB = [&](int kt) {
#pragma unroll
        for (int i = 0; i < 2; i++) {
            int idx = tid + i * 256;
            int r = idx >> 3, c = (idx & 7) * 4;
            rBg[i] = *(const float4*)(Bgp + (size_t)(nBase + r) * H + kt * BK + c);
            rBu[i] = *(const float4*)(Bup + (size_t)(nBase + r) * H + kt * BK + c);
        }
    };
    auto stB = [&](int buf) {
        float* sg = sBg + buf * BN * PAD;
        float* su = sBu + buf * BN * PAD;
#pragma unroll
        for (int i = 0; i < 2; i++) {
            int idx = tid + i * 256;
            int r = idx >> 3, c = (idx & 7) * 4;
            float4 v = rBg[i], w;
            w.x = f2tf(v.x); w.y = f2tf(v.y); w.z = f2tf(v.z); w.w = f2tf(v.w);
            *(float4*)(sg + r * PAD + c) = w;
            v = rBu[i];
            w.x = f2tf(v.x); w.y = f2tf(v.y); w.z = f2tf(v.z); w.w = f2tf(v.w);
            *(float4*)(su + r * PAD + c) = w;
        }
    };

    int lane = tid & 31, warp = tid >> 5;
    int wm = (warp & 3) * 32;
    int wn = (warp >> 2) * 32;
    int g4 = lane >> 2, t4 = lane & 3;

    float acc1[2][4][4] = {}, acc2[2][4][4] = {};

    loadA(0, 0); cp_commit();
    ldgB(0);
    cp_wait0();
    stB(0);
    __syncthreads();
    int buf = 0;
    for (int kt = 0; kt < KT; kt++) {
        if (kt + 1 < KT) { loadA(kt + 1, buf ^ 1); cp_commit(); ldgB(kt + 1); }
        const float* A   = sA  + buf * BM * PAD;
        const float* Bgs = sBg + buf * BN * PAD;
        const float* Bus = sBu + buf * BN * PAD;
#pragma unroll
        for (int ks = 0; ks < BK / 8; ks++) {
            int kc = ks * 8 + t4;
            uint32_t a[2][4], bg[4][2], bu[4][2];
#pragma unroll
            for (int mt = 0; mt < 2; mt++) {
                int r = wm + mt * 16;
                a[mt][0] = __float_as_uint(A[(r + g4)     * PAD + kc]);
                a[mt][1] = __float_as_uint(A[(r + 8 + g4) * PAD + kc]);
                a[mt][2] = __float_as_uint(A[(r + g4)     * PAD + kc + 4]);
                a[mt][3] = __float_as_uint(A[(r + 8 + g4) * PAD + kc + 4]);
            }
#pragma unroll
            for (int nt = 0; nt < 4; nt++) {
                int n = wn + nt * 8 + g4;
                bg[nt][0] = __float_as_uint(Bgs[n * PAD + kc]);
                bg[nt][1] = __float_as_uint(Bgs[n * PAD + kc + 4]);
                bu[nt][0] = __float_as_uint(Bus[n * PAD + kc]);
                bu[nt][1] = __float_as_uint(Bus[n * PAD + kc + 4]);
            }
#pragma unroll
            for (int mt = 0; mt < 2; mt++)
#pragma unroll
                for (int nt = 0; nt < 4; nt++) {
                    mma8(acc1[mt][nt], a[mt], bg[nt]);
                    mma8(acc2[mt][nt], a[mt], bu[nt]);
                }
        }
        if (kt + 1 < KT) { cp_wait0(); stB(buf ^ 1); __syncthreads(); buf ^= 1; }
    }
    // SwiGLU epilogue -> G (tf32-rounded)
#pragma unroll
    for (int mt = 0; mt < 2; mt++)
#pragma unroll
        for (int nt = 0; nt < 4; nt++)
#pragma unroll
            for (int i = 0; i < 4; i++) {
                int r = aRow + wm + mt * 16 + g4 + ((i >> 1) << 3);
                int c = nBase + wn + nt * 8 + t4 * 2 + (i & 1);
                float c1 = acc1[mt][nt][i], c2 = acc2[mt][nt][i];
                float sv = c1 / (1.f + __expf(-c1));
                g_G[(size_t)r * GSTRIDE + c] = f2tf(sv * c2);
            }
}

// -------------------- kernel 5: grouped GEMM2 (down proj) --------------------
// Y = G @ Wd^T.   K = F (routed) or FS (shared), N = H.
__global__ void __launch_bounds__(256) k_gemm2(const float* __restrict__ wd,
                                               const float* __restrict__ swd) {
    int grp = blockIdx.z;
    if ((int)blockIdx.y >= g_mtiles[grp]) return;
    int Kd = (grp < E) ? F : FS;
    const float* Bp = (grp < E) ? wd + (size_t)grp * H * F : swd;
    int nBase = blockIdx.x * BN;                 // N = H, always in range
    int aRow = g_row0[grp] + blockIdx.y * BM;

    extern __shared__ float sm[];
    float* sA = sm;                              // 2 * BM*PAD
    float* sB = sm + 2 * BM * PAD;               // 2 * BN*PAD

    int tid = threadIdx.x;
    const int KT = Kd / BK;                      // 44 or 88
    float4 rB[2];

    auto loadA = [&](int kt, int buf) {
        const float* gA = g_G + (size_t)aRow * GSTRIDE + kt * BK;
        float* s = sA + buf * BM * PAD;
#pragma unroll
        for (int i = 0; i < 4; i++) {
            int idx = tid + i * 256;
            int r = idx >> 3, c = (idx & 7) * 4;
            cpa16(s + r * PAD + c, gA + (size_t)r * GSTRIDE + c);
        }
    };
    auto ldgB = [&](int kt) {
#pragma unroll
        for (int i = 0; i < 2; i++) {
            int idx = tid + i * 256;
            int r = idx >> 3, c = (idx & 7) * 4;
            rB[i] = *(const float4*)(Bp + (size_t)(nBase + r) * Kd + kt * BK + c);
        }
    };
    auto stB = [&](int buf) {
        float* s = sB + buf * BN * PAD;
#pragma unroll
        for (int i = 0; i < 2; i++) {
            int idx = tid + i * 256;
            int r = idx >> 3, c = (idx & 7) * 4;
            float4 v = rB[i], w;
            w.x = f2tf(v.x); w.y = f2tf(v.y); w.z = f2tf(v.z); w.w = f2tf(v.w);
            *(float4*)(s + r * PAD + c) = w;
        }
    };

    int lane = tid & 31, warp = tid >> 5;
    int wm = (warp & 3) * 32;
    int wn = (warp >> 2) * 32;
    int g4 = lane >> 2, t4 = lane & 3;

    float acc[2][4][4] = {};

    loadA(0, 0); cp_commit();
    ldgB(0);
    cp_wait0();
    stB(0);
    __syncthreads();
    int buf = 0;
    for (int kt = 0; kt < KT; kt++) {
        if (kt + 1 < KT) { loadA(kt + 1, buf ^ 1); cp_commit(); ldgB(kt + 1); }
        const float* A  = sA + buf * BM * PAD;
        const float* Bs = sB + buf * BN * PAD;
#pragma unroll
        for (int ks = 0; ks < BK / 8; ks++) {
            int kc = ks * 8 + t4;
            uint32_t a[2][4], b[4][2];
#pragma unroll
            for (int mt = 0; mt < 2; mt++) {
                int r = wm + mt * 16;
                a[mt][0] = __float_as_uint(A[(r + g4)     * PAD + kc]);
                a[mt][1] = __float_as_uint(A[(r + 8 + g4) * PAD + kc]);
                a[mt][2] = __float_as_uint(A[(r + g4)     * PAD + kc + 4]);
                a[mt][3] = __float_as_uint(A[(r + 8 + g4) * PAD + kc + 4]);
            }
#pragma unroll
            for (int nt = 0; nt < 4; nt++) {
                int n = wn + nt * 8 + g4;
                b[nt][0] = __float_as_uint(Bs[n * PAD + kc]);
                b[nt][1] = __float_as_uint(Bs[n * PAD + kc + 4]);
            }
#pragma unroll
            for (int mt = 0; mt < 2; mt++)
#pragma unroll
                for (int nt = 0; nt < 4; nt++)
                    mma8(acc[mt][nt], a[mt], b[nt]);
        }
        if (kt + 1 < KT) { cp_wait0(); stB(buf ^ 1); __syncthreads(); buf ^= 1; }
    }
#pragma unroll
    for (int mt = 0; mt < 2; mt++)
#pragma unroll
        for (int nt = 0; nt < 4; nt++)
#pragma unroll
            for (int i = 0; i < 4; i++) {
                int r = aRow + wm + mt * 16 + g4 + ((i >> 1) << 3);
                int c = nBase + wn + nt * 8 + t4 * 2 + (i & 1);
                g_Y[(size_t)r * H + c] = acc[mt][nt][i];
            }
}

// -------------------- kernel 6: combine --------------------
__global__ void __launch_bounds__(256) k_comb(float* __restrict__ out) {
    int t = blockIdx.x;
    int r0 = g_rowof[2 * t], r1 = g_rowof[2 * t + 1];
    float w0 = g_tkw[2 * t], w1 = g_tkw[2 * t + 1];
    int rs = g_row0[E] + t;
    const float4* y0 = (const float4*)(g_Y + (size_t)r0 * H);
    const float4* y1 = (const float4*)(g_Y + (size_t)r1 * H);
    const float4* ys = (const float4*)(g_Y + (size_t)rs * H);
    float4* o = (float4*)(out + (size_t)t * H);
    for (int i = threadIdx.x; i < H / 4; i += blockDim.x) {
        float4 a = y0[i], b = y1[i], c = ys[i], r;
        r.x = fmaf(w0, a.x, fmaf(w1, b.x, c.x));
        r.y = fmaf(w0, a.y, fmaf(w1, b.y, c.y));
        r.z = fmaf(w0, a.z, fmaf(w1, b.z, c.z));
        r.w = fmaf(w0, a.w, fmaf(w1, b.w, c.w));
        o[i] = r;
    }
}

// -------------------- host launcher --------------------
extern "C" void kernel_launch(void* const* d_in, const int* in_sizes, int n_in,
                              void* d_out, int out_size) {
    const float* x   = (const float*)d_in[0];
    const float* gw  = (const float*)d_in[1];
    const float* wg  = (const float*)d_in[2];
    const float* wu  = (const float*)d_in[3];
    const float* wd  = (const float*)d_in[4];
    const float* swg = (const float*)d_in[5];
    const float* swu = (const float*)d_in[6];
    const float* swd = (const float*)d_in[7];
    float* out = (float*)d_out;

    const int SMEM1 = (2 * BM * PAD + 4 * BN * PAD) * 4;  // 73728 B
    const int SMEM2 = (2 * BM * PAD + 2 * BN * PAD) * 4;  // 55296 B
    cudaFuncSetAttribute(k_gemm1, cudaFuncAttributeMaxDynamicSharedMemorySize, SMEM1);
    cudaFuncSetAttribute(k_gemm2, cudaFuncAttributeMaxDynamicSharedMemorySize, SMEM2);

    k_zero<<<1, 32>>>();
    k_gate<<<T / 8, 256>>>(x, gw);
    k_scan<<<1, 1>>>();
    k_gather<<<3 * T, 256>>>(x);
    k_gemm1<<<dim3(FS / BN, 16, E + 1), 256, SMEM1>>>(wg, wu, swg, swu);
    k_gemm2<<<dim3(H / BN, 16, E + 1), 256, SMEM2>>>(wd, swd);
    k_comb<<<T, 256>>>(out);
}

// round 3
// speedup vs baseline: 1.7700x; 1.7700x over previous
#include <cuda_runtime.h>
#include <cuda_fp16.h>
#include <cstdint>

// ---------------- problem constants ----------------
#define H   2048
#define F   1408
#define FS  2816
#define E   8
#define T   2048
#define GSTRIDE 2816
#define MAXROWS 7424

// ---------------- GEMM tiling (fp16 mma.sync m16n8k16) ----------------
#define BM  128
#define BN  128
#define BK  64                       // halves per stage (128 B/row)
#define SAB 72                       // smem row stride in halves (144 B, pad 16B)
#define TILE_BYTES (128 * SAB * 2)   // 18432 B per tile buffer
#define SMEM_TOTAL (4 * TILE_BYTES)  // A0,B0,A1,B1 = 73728 B

// ---------------- device scratch (alloc-free rule) ----------------
__device__ __half g_XG[(size_t)MAXROWS * H];
__device__ __half g_G [(size_t)MAXROWS * GSTRIDE];
__device__ float  g_Y [(size_t)MAXROWS * H];
__device__ __half g_rw1 [(size_t)E * 2 * F * H];   // routed gate/up interleaved rows
__device__ __half g_rsw1[(size_t)2 * FS * H];      // shared gate/up interleaved
__device__ __half g_rwd [(size_t)E * H * F];
__device__ __half g_rswd[(size_t)H * FS];
__device__ int   g_cnt[E];
__device__ int   g_cursor[E];
__device__ int   g_row0[E + 1];
__device__ int   g_mtiles[E + 1];
__device__ int   g_rowof[2 * T];
__device__ int   g_tke[2 * T];
__device__ float g_tkw[2 * T];

// ---------------- helpers ----------------
__device__ __forceinline__ uint32_t smem_u32(const void* p) {
    uint32_t a;
    asm("{ .reg .u64 t; cvta.to.shared.u64 t, %1; cvt.u32.u64 %0, t; }" : "=r"(a) : "l"(p));
    return a;
}
__device__ __forceinline__ void cp16(uint32_t s, const void* g) {
    asm volatile("cp.async.cg.shared.global [%0], [%1], 16;" :: "r"(s), "l"(g));
}
__device__ __forceinline__ void ldsm4(uint32_t& r0, uint32_t& r1, uint32_t& r2, uint32_t& r3,
                                      uint32_t a) {
    asm volatile("ldmatrix.sync.aligned.m8n8.x4.shared.b16 {%0,%1,%2,%3}, [%4];"
                 : "=r"(r0), "=r"(r1), "=r"(r2), "=r"(r3) : "r"(a));
}
__device__ __forceinline__ void mma16(float* d, const uint32_t* a, const uint32_t* b) {
    asm volatile(
        "mma.sync.aligned.m16n8k16.row.col.f32.f16.f16.f32 "
        "{%0,%1,%2,%3},{%4,%5,%6,%7},{%8,%9},{%0,%1,%2,%3};"
        : "+f"(d[0]), "+f"(d[1]), "+f"(d[2]), "+f"(d[3])
        : "r"(a[0]), "r"(a[1]), "r"(a[2]), "r"(a[3]), "r"(b[0]), "r"(b[1]));
}
__device__ __forceinline__ uint2 f4_to_h4(float4 v) {
    __half2 lo = __floats2half2_rn(v.x, v.y);
    __half2 hi = __floats2half2_rn(v.z, v.w);
    uint2 r;
    r.x = *(uint32_t*)&lo;
    r.y = *(uint32_t*)&hi;
    return r;
}

// ---------------- kernel 0: zero counters ----------------
__global__ void k_zero() {
    if (threadIdx.x < E) g_cnt[threadIdx.x] = 0;
}

// ---------------- conversion: gate/up fp32 -> fp16 interleaved rows ----------------
// dst row j (within a group of 2*rowsF): even j -> gate row j/2, odd -> up row j/2.
__global__ void __launch_bounds__(128) k_cvt1(const float* __restrict__ wg,
                                              const float* __restrict__ wu,
                                              __half* __restrict__ dst, int rowsF) {
    int j = blockIdx.x;                       // 0 .. nGroups*2*rowsF-1
    int grp2 = j / (2 * rowsF);
    int j2 = j - grp2 * 2 * rowsF;
    const float* src = ((j2 & 1) ? wu : wg) + ((size_t)grp2 * rowsF + (j2 >> 1)) * H;
    uint2* d = (uint2*)(dst + (size_t)j * H);
    const float4* s = (const float4*)src;
#pragma unroll
    for (int i = 0; i < 4; i++)
        d[threadIdx.x + i * 128] = f4_to_h4(s[threadIdx.x + i * 128]);
}

// ---------------- conversion: plain fp32 -> fp16 ----------------
__global__ void __launch_bounds__(256) k_cvt(const float* __restrict__ src,
                                             __half* __restrict__ dst, int n4) {
    int stride = gridDim.x * blockDim.x;
    const float4* s = (const float4*)src;
    uint2* d = (uint2*)dst;
    for (int i = blockIdx.x * blockDim.x + threadIdx.x; i < n4; i += stride)
        d[i] = f4_to_h4(s[i]);
}

// ---------------- kernel 1: gating (fp32 exact) ----------------
__global__ void __launch_bounds__(256) k_gate(const float* __restrict__ x,
                                              const float* __restrict__ gw) {
    int warp = (blockIdx.x * blockDim.x + threadIdx.x) >> 5;
    int lane = threadIdx.x & 31;
    if (warp >= T) return;
    const float* xr = x + (size_t)warp * H;
    float xv[H / 32];
#pragma unroll
    for (int i = 0; i < H / 32; i++) xv[i] = xr[lane + i * 32];
    float sc[E];
#pragma unroll
    for (int e = 0; e < E; e++) {
        const float* w = gw + (size_t)e * H;
        float a = 0.f;
#pragma unroll
        for (int i = 0; i < H / 32; i++) a += xv[i] * w[lane + i * 32];
#pragma unroll
        for (int o = 16; o > 0; o >>= 1) a += __shfl_xor_sync(0xffffffffu, a, o);
        sc[e] = a;
    }
    if (lane == 0) {
        float mx = sc[0];
#pragma unroll
        for (int e = 1; e < E; e++) mx = fmaxf(mx, sc[e]);
        float s = 0.f;
#pragma unroll
        for (int e = 0; e < E; e++) { sc[e] = expf(sc[e] - mx); s += sc[e]; }
        float inv_s = 1.f / s;
#pragma unroll
        for (int e = 0; e < E; e++) sc[e] *= inv_s;
        int e0 = 0;
#pragma unroll
        for (int e = 1; e < E; e++) if (sc[e] > sc[e0]) e0 = e;
        int e1 = -1;
#pragma unroll
        for (int e = 0; e < E; e++)
            if (e != e0 && (e1 < 0 || sc[e] > sc[e1])) e1 = e;
        float w0 = sc[e0], w1 = sc[e1];
        float inv = 1.f / (w0 + w1 + 1e-20f);
        g_tke[2 * warp]     = e0;
        g_tke[2 * warp + 1] = e1;
        g_tkw[2 * warp]     = w0 * inv;
        g_tkw[2 * warp + 1] = w1 * inv;
        atomicAdd(&g_cnt[e0], 1);
        atomicAdd(&g_cnt[e1], 1);
    }
}

// ---------------- kernel 2: scan ----------------
__global__ void k_scan() {
    if (threadIdx.x == 0 && blockIdx.x == 0) {
        int off = 0;
        for (int e = 0; e < E; e++) {
            g_row0[e]   = off;
            g_cursor[e] = off;
            int mt = (g_cnt[e] + 127) >> 7;
            g_mtiles[e] = mt;
            off += mt << 7;
        }
        g_row0[E]   = off;
        g_mtiles[E] = T >> 7;
    }
}

// ---------------- kernel 3: gather (fp16 rows) ----------------
__global__ void __launch_bounds__(256) k_gather(const float* __restrict__ x) {
    __shared__ int sp;
    int b = blockIdx.x;
    int t, p;
    if (b < 2 * T) {
        if (threadIdx.x == 0) {
            int e = g_tke[b];
            int q = atomicAdd(&g_cursor[e], 1);
            g_rowof[b] = q;
            sp = q;
        }
        __syncthreads();
        p = sp;
        t = b >> 1;
    } else {
        t = b - 2 * T;
        p = g_row0[E] + t;
    }
    const float4* src = (const float4*)(x + (size_t)t * H);
    uint2* dst = (uint2*)(g_XG + (size_t)p * H);
#pragma unroll
    for (int i = 0; i < 2; i++)
        dst[threadIdx.x + i * 256] = f4_to_h4(src[threadIdx.x + i * 256]);
}

// ====================== GEMM core (fp16, m16n8k16, 128x128x64) ======================
// warp layout: warpM = wid&3 (M 32/warp), warpN = wid>>2 (N 64/warp)
struct GemmCtx {
    uint32_t sA[2], sB[2];      // smem base addrs per buffer
    const __half* gA;           // A base (row aRow, col 0), row stride ldA
    const __half* gB;           // B base (row nBase, col 0), row stride ldB
    int ldA, ldB;
};

__device__ __forceinline__ void gemm_fill(const GemmCtx& c, int kt, int buf, int tid) {
    const __half* gA = c.gA + kt * BK;
    const __half* gB = c.gB + kt * BK;
#pragma unroll
    for (int i = 0; i < 4; i++) {
        int ch = tid + i * 256;
        int r = ch >> 3, cc = ch & 7;
        cp16(c.sA[buf] + r * 144 + cc * 16, gA + (size_t)r * c.ldA + cc * 8);
    }
#pragma unroll
    for (int i = 0; i < 4; i++) {
        int ch = tid + i * 256;
        int r = ch >> 3, cc = ch & 7;
        cp16(c.sB[buf] + r * 144 + cc * 16, gB + (size_t)r * c.ldB + cc * 8);
    }
}

__device__ __forceinline__ void gemm_compute(const GemmCtx& c, int buf,
                                             int warpM, int warpN, int lane,
                                             float acc[2][8][4]) {
    uint32_t aBase = c.sA[buf] + (warpM * 32 + (lane & 15)) * 144 + ((lane >> 4) << 4);
    uint32_t bBase = c.sB[buf] +
                     (warpN * 64 + (lane & 7) + ((lane >> 4) << 3)) * 144 +
                     (((lane >> 3) & 1) << 4);
#pragma unroll
    for (int kk = 0; kk < BK / 16; kk++) {
        uint32_t af[2][4], bf[8][2];
#pragma unroll
        for (int mt = 0; mt < 2; mt++)
            ldsm4(af[mt][0], af[mt][1], af[mt][2], af[mt][3],
                  aBase + mt * 16 * 144 + kk * 32);
#pragma unroll
        for (int p = 0; p < 4; p++)
            ldsm4(bf[2 * p][0], bf[2 * p][1], bf[2 * p + 1][0], bf[2 * p + 1][1],
                  bBase + p * 16 * 144 + kk * 32);
#pragma unroll
        for (int mt = 0; mt < 2; mt++)
#pragma unroll
            for (int nt = 0; nt < 8; nt++)
                mma16(acc[mt][nt], af[mt], bf[nt]);
    }
}

#define GEMM_MAINLOOP(ctx, KT, tid, warpM, warpN, lane, acc)                      \
    {                                                                             \
        int buf = 0;                                                              \
        gemm_fill(ctx, 0, 0, tid);                                                \
        asm volatile("cp.async.commit_group;");                                   \
        for (int kt = 0; kt < (KT); kt++) {                                       \
            if (kt + 1 < (KT)) {                                                  \
                gemm_fill(ctx, kt + 1, buf ^ 1, tid);                             \
                asm volatile("cp.async.commit_group;");                           \
                asm volatile("cp.async.wait_group 1;");                           \
            } else {                                                              \
                asm volatile("cp.async.wait_group 0;");                           \
            }                                                                     \
            __syncthreads();                                                      \
            gemm_compute(ctx, buf, warpM, warpN, lane, acc);                      \
            __syncthreads();                                                      \
            buf ^= 1;                                                             \
        }                                                                         \
    }

// ---------------- GEMM1: x @ [gate|up interleaved]^T, SwiGLU epilogue ----------------
__global__ void __launch_bounds__(256) k_gemm1() {
    int grp = blockIdx.z;
    if ((int)blockIdx.y >= g_mtiles[grp]) return;
    int N2 = (grp < E) ? 2 * F : 2 * FS;
    int nBase = blockIdx.x * BN;
    if (nBase >= N2) return;
    const __half* Bsrc = (grp < E) ? g_rw1 + (size_t)grp * 2 * F * H : g_rsw1;
    int aRow = g_row0[grp] + blockIdx.y * BM;

    extern __shared__ char smem[];
    uint32_t sb = smem_u32(smem);
    int tid = threadIdx.x, lane = tid & 31, wid = tid >> 5;
    int warpM = wid & 3, warpN = wid >> 2;

    GemmCtx c;
    c.sA[0] = sb;                 c.sB[0] = sb + TILE_BYTES;
    c.sA[1] = sb + 2 * TILE_BYTES; c.sB[1] = sb + 3 * TILE_BYTES;
    c.gA = g_XG + (size_t)aRow * H;      c.ldA = H;
    c.gB = Bsrc + (size_t)nBase * H;     c.ldB = H;

    float acc[2][8][4];
#pragma unroll
    for (int a = 0; a < 2; a++)
#pragma unroll
        for (int b = 0; b < 8; b++)
#pragma unroll
            for (int k = 0; k < 4; k++) acc[a][b][k] = 0.f;

    GEMM_MAINLOOP(c, H / BK, tid, warpM, warpN, lane, acc);

    // SwiGLU: even col = gate, odd col = up; each thread's (c0,c1)/(c2,c3) are pairs
    int g4 = lane >> 2, t4 = lane & 3;
    int fHalf = (nBase >> 1) + warpN * 32;
#pragma unroll
    for (int mt = 0; mt < 2; mt++) {
        int r0 = aRow + warpM * 32 + mt * 16 + g4;
#pragma unroll
        for (int nt = 0; nt < 8; nt++) {
            int f = fHalf + nt * 4 + t4;
            float cg = acc[mt][nt][0], cu = acc[mt][nt][1];
            g_G[(size_t)r0 * GSTRIDE + f] = __float2half_rn(cg / (1.f + __expf(-cg)) * cu);
            cg = acc[mt][nt][2]; cu = acc[mt][nt][3];
            g_G[(size_t)(r0 + 8) * GSTRIDE + f] = __float2half_rn(cg / (1.f + __expf(-cg)) * cu);
        }
    }
}

// ---------------- GEMM2: G @ Wd^T -> Y (fp32) ----------------
__global__ void __launch_bounds__(256) k_gemm2() {
    int grp = blockIdx.z;
    if ((int)blockIdx.y >= g_mtiles[grp]) return;
    int Kd = (grp < E) ? F : FS;
    const __half* Bd = (grp < E) ? g_rwd + (size_t)grp * H * F : g_rswd;
    int nBase = blockIdx.x * BN;
    int aRow = g_row0[grp] + blockIdx.y * BM;

    extern __shared__ char smem[];
    uint32_t sb = smem_u32(smem);
    int tid = threadIdx.x, lane = tid & 31, wid = tid >> 5;
    int warpM = wid & 3, warpN = wid >> 2;

    GemmCtx c;
    c.sA[0] = sb;                 c.sB[0] = sb + TILE_BYTES;
    c.sA[1] = sb + 2 * TILE_BYTES; c.sB[1] = sb + 3 * TILE_BYTES;
    c.gA = g_G + (size_t)aRow * GSTRIDE;  c.ldA = GSTRIDE;
    c.gB = Bd + (size_t)nBase * Kd;       c.ldB = Kd;

    float acc[2][8][4];
#pragma unroll
    for (int a = 0; a < 2; a++)
#pragma unroll
        for (int b = 0; b < 8; b++)
#pragma unroll
            for (int k = 0; k < 4; k++) acc[a][b][k] = 0.f;

    GEMM_MAINLOOP(c, Kd / BK, tid, warpM, warpN, lane, acc);

    int g4 = lane >> 2, t4 = lane & 3;
#pragma unroll
    for (int mt = 0; mt < 2; mt++) {
        int r0 = aRow + warpM * 32 + mt * 16 + g4;
#pragma unroll
        for (int nt = 0; nt < 8; nt++) {
            int col = nBase + warpN * 64 + nt * 8 + 2 * t4;
            *(float2*)(g_Y + (size_t)r0 * H + col) =
                make_float2(acc[mt][nt][0], acc[mt][nt][1]);
            *(float2*)(g_Y + (size_t)(r0 + 8) * H + col) =
                make_float2(acc[mt][nt][2], acc[mt][nt][3]);
        }
    }
}

// ---------------- kernel 6: combine ----------------
__global__ void __launch_bounds__(256) k_comb(float* __restrict__ out) {
    int t = blockIdx.x;
    int r0 = g_rowof[2 * t], r1 = g_rowof[2 * t + 1];
    float w0 = g_tkw[2 * t], w1 = g_tkw[2 * t + 1];
    int rs = g_row0[E] + t;
    const float4* y0 = (const float4*)(g_Y + (size_t)r0 * H);
    const float4* y1 = (const float4*)(g_Y + (size_t)r1 * H);
    const float4* ys = (const float4*)(g_Y + (size_t)rs * H);
    float4* o = (float4*)(out + (size_t)t * H);
    for (int i = threadIdx.x; i < H / 4; i += blockDim.x) {
        float4 a = y0[i], b = y1[i], c = ys[i], r;
        r.x = fmaf(w0, a.x, fmaf(w1, b.x, c.x));
        r.y = fmaf(w0, a.y, fmaf(w1, b.y, c.y));
        r.z = fmaf(w0, a.z, fmaf(w1, b.z, c.z));
        r.w = fmaf(w0, a.w, fmaf(w1, b.w, c.w));
        o[i] = r;
    }
}

// ---------------- host launcher ----------------
extern "C" void kernel_launch(void* const* d_in, const int* in_sizes, int n_in,
                              void* d_out, int out_size) {
    const float* x   = (const float*)d_in[0];
    const float* gw  = (const float*)d_in[1];
    const float* wg  = (const float*)d_in[2];
    const float* wu  = (const float*)d_in[3];
    const float* wd  = (const float*)d_in[4];
    const float* swg = (const float*)d_in[5];
    const float* swu = (const float*)d_in[6];
    const float* swd = (const float*)d_in[7];
    float* out = (float*)d_out;

    cudaFuncSetAttribute(k_gemm1, cudaFuncAttributeMaxDynamicSharedMemorySize, SMEM_TOTAL);
    cudaFuncSetAttribute(k_gemm2, cudaFuncAttributeMaxDynamicSharedMemorySize, SMEM_TOTAL);

    __half *p_rw1, *p_rsw1, *p_rwd, *p_rswd;
    cudaGetSymbolAddress((void**)&p_rw1,  g_rw1);
    cudaGetSymbolAddress((void**)&p_rsw1, g_rsw1);
    cudaGetSymbolAddress((void**)&p_rwd,  g_rwd);
    cudaGetSymbolAddress((void**)&p_rswd, g_rswd);

    k_zero<<<1, 32>>>();
    k_gate<<<T / 8, 256>>>(x, gw);
    k_scan<<<1, 1>>>();
    k_gather<<<3 * T, 256>>>(x);

    k_cvt1<<<E * 2 * F, 128>>>(wg, wu, p_rw1, F);       // routed gate/up interleave
    k_cvt1<<<2 * FS, 128>>>(swg, swu, p_rsw1, FS);      // shared gate/up interleave
    k_cvt<<<1184, 256>>>(wd, p_rwd, E * H * F / 4);
    k_cvt<<<1184, 256>>>(swd, p_rswd, H * FS / 4);

    k_gemm1<<<dim3(2 * FS / BN, 32, E + 1), 256, SMEM_TOTAL>>>();
    k_gemm2<<<dim3(H / BN, 32, E + 1), 256, SMEM_TOTAL>>>();
    k_comb<<<T, 256>>>(out);
}